// round 1
// baseline (speedup 1.0000x reference)
#include <cuda_runtime.h>
#include <math.h>

#define Bx 8
#define Nx 1024
#define Cx 64
#define Ox 64
#define Mx 4                 // K+1
#define BN (Bx*Nx)           // 8192
#define BNO (BN*Ox)          // 524288

// ---------------- scratch (device globals; no allocations allowed) ----------
__device__ float g_sRi[BN], g_sIi[BN], g_sRj[BN], g_sIj[BN];
__device__ float g_cmax[BN], g_rsum[BN];
__device__ float g_rowR[Bx*Mx*Nx], g_rowI[Bx*Mx*Nx];

// ---------------- kernel A: attention projections ---------------------------
// one warp per (b,n) row: 8 partial dots, butterfly-reduced.
__global__ void __launch_bounds__(256) kA(const float* __restrict__ Xr,
                                          const float* __restrict__ Xi,
                                          const float* __restrict__ awr,
                                          const float* __restrict__ awi)
{
    int gw   = (blockIdx.x * blockDim.x + threadIdx.x) >> 5;
    int lane = threadIdx.x & 31;
    if (gw >= BN) return;
    const float* xr = Xr + (size_t)gw * Cx;
    const float* xi = Xi + (size_t)gw * Cx;
    float a1=0.f,a2=0.f,a3=0.f,a4=0.f,a5=0.f,a6=0.f,a7=0.f,a8=0.f;
#pragma unroll
    for (int k = 0; k < 2; k++) {
        int c = lane + (k << 5);
        float xrv = xr[c], xiv = xi[c];
        float wri = awr[c],      wii = awi[c];
        float wrj = awr[Cx + c], wij = awi[Cx + c];
        a1 = fmaf(xrv, wri, a1);  a2 = fmaf(xiv, wii, a2);
        a3 = fmaf(xrv, wii, a3);  a4 = fmaf(xiv, wri, a4);
        a5 = fmaf(xrv, wrj, a5);  a6 = fmaf(xiv, wij, a6);
        a7 = fmaf(xrv, wij, a7);  a8 = fmaf(xiv, wrj, a8);
    }
#pragma unroll
    for (int off = 16; off; off >>= 1) {
        a1 += __shfl_xor_sync(0xffffffffu, a1, off);
        a2 += __shfl_xor_sync(0xffffffffu, a2, off);
        a3 += __shfl_xor_sync(0xffffffffu, a3, off);
        a4 += __shfl_xor_sync(0xffffffffu, a4, off);
        a5 += __shfl_xor_sync(0xffffffffu, a5, off);
        a6 += __shfl_xor_sync(0xffffffffu, a6, off);
        a7 += __shfl_xor_sync(0xffffffffu, a7, off);
        a8 += __shfl_xor_sync(0xffffffffu, a8, off);
    }
    if (lane == 0) {
        g_sRi[gw] = a1 - a2;
        g_sIi[gw] = a3 + a4;
        g_sRj[gw] = a5 - a6;
        g_sIj[gw] = a7 + a8;
    }
}

// ---------------- kernel B: per-(b,j) softmax stats over i ------------------
// grid: 8 * 256 blocks; each block handles 4 j columns, 256 threads over i.
__global__ void __launch_bounds__(256) kB(const float* __restrict__ br,
                                          const float* __restrict__ bi,
                                          const float* __restrict__ par,
                                          const float* __restrict__ pai)
{
    __shared__ float sri_s[Nx], sii_s[Nx];
    __shared__ float red[8];
    int b  = blockIdx.x >> 8;
    int j0 = (blockIdx.x & 255) << 2;
    float biasr = br[0], biasi = bi[0];
    float apr = par[0], api = pai[0];
    for (int t = threadIdx.x; t < Nx; t += 256) {
        sri_s[t] = g_sRi[b*Nx + t] + biasr;
        sii_s[t] = g_sIi[b*Nx + t] + biasi;
    }
    __syncthreads();
    int lane = threadIdx.x & 31, wid = threadIdx.x >> 5;
    for (int jj = 0; jj < 4; jj++) {
        int j = j0 + jj;
        float sjr = g_sRj[b*Nx + j];
        float sji = g_sIj[b*Nx + j];
        float mags[4];
        float lmax = -1e30f;
#pragma unroll
        for (int k = 0; k < 4; k++) {
            int i = threadIdx.x + (k << 8);
            float scr = sri_s[i] + sjr;
            float sci = sii_s[i] + sji;
            float pr = scr >= 0.f ? scr : apr * scr;
            float pi = sci >= 0.f ? sci : api * sci;
            float s2 = fmaf(pr, pr, pi * pi);
            float rm = rsqrtf(fmaxf(s2, 1e-36f));
            float mg = s2 * rm;
            mags[k] = mg;
            lmax = fmaxf(lmax, mg);
        }
#pragma unroll
        for (int off = 16; off; off >>= 1)
            lmax = fmaxf(lmax, __shfl_xor_sync(0xffffffffu, lmax, off));
        if (lane == 0) red[wid] = lmax;
        __syncthreads();
        float M = red[0];
#pragma unroll
        for (int t = 1; t < 8; t++) M = fmaxf(M, red[t]);
        __syncthreads();                 // everyone has M; safe to reuse red
        float ls = 0.f;
#pragma unroll
        for (int k = 0; k < 4; k++) ls += __expf(mags[k] - M);
#pragma unroll
        for (int off = 16; off; off >>= 1)
            ls += __shfl_xor_sync(0xffffffffu, ls, off);
        if (lane == 0) red[wid] = ls;
        __syncthreads();
        if (threadIdx.x == 0) {
            float S = red[0]+red[1]+red[2]+red[3]+red[4]+red[5]+red[6]+red[7];
            g_cmax[b*Nx + j] = M;
            g_rsum[b*Nx + j] = 1.0f / S;
        }
        __syncthreads();                 // before next jj reuses red
    }
}

// ---------------- kernel C: the 268 MB L reduction (HBM-bound) --------------
// grid: 8 * 128 blocks, 8 warps/block, one warp per i-row; all 4 m's fused so
// ar/ai are computed exactly once per (b,i,j).
__global__ void __launch_bounds__(256) kC(const float* __restrict__ Lr,
                                          const float* __restrict__ Li,
                                          const float* __restrict__ br,
                                          const float* __restrict__ bi,
                                          const float* __restrict__ par,
                                          const float* __restrict__ pai)
{
    __shared__ float sjr_s[Nx], sji_s[Nx], cm_s[Nx], rs_s[Nx];
    int b  = blockIdx.x >> 7;
    int i0 = (blockIdx.x & 127) << 3;
    for (int t = threadIdx.x; t < Nx; t += 256) {
        sjr_s[t] = g_sRj[b*Nx + t];
        sji_s[t] = g_sIj[b*Nx + t];
        cm_s[t]  = g_cmax[b*Nx + t];
        rs_s[t]  = g_rsum[b*Nx + t];
    }
    __syncthreads();
    int wid = threadIdx.x >> 5, lane = threadIdx.x & 31;
    int i = i0 + wid;
    float sri = g_sRi[b*Nx + i] + br[0];
    float sii = g_sIi[b*Nx + i] + bi[0];
    float apr = par[0], api = pai[0];
    const size_t MS = (size_t)Nx * Nx;
    const float* pR = Lr + (size_t)b * Mx * MS + (size_t)i * Nx;
    const float* pI = Li + (size_t)b * Mx * MS + (size_t)i * Nx;

    float aR0=0.f,aR1=0.f,aR2=0.f,aR3=0.f;
    float aI0=0.f,aI1=0.f,aI2=0.f,aI3=0.f;

#pragma unroll 1
    for (int jb = 0; jb < Nx; jb += 64) {
#pragma unroll
        for (int u = 0; u < 2; u++) {
            int j = jb + (u << 5) + lane;
            float scr = sri + sjr_s[j];
            float sci = sii + sji_s[j];
            float pr = scr >= 0.f ? scr : apr * scr;
            float pi = sci >= 0.f ? sci : api * sci;
            float s2 = fmaf(pr, pr, pi * pi);
            float rm = rsqrtf(fmaxf(s2, 1e-36f));
            float mg = s2 * rm;                          // == |p|
            float sc = __fdividef(__expf(mg - cm_s[j]) * rs_s[j], mg + 1e-12f);
            float ar = sc * pr, ai = sc * pi;
            float l0 = __ldcs(pR + j);
            float l1 = __ldcs(pR + MS + j);
            float l2 = __ldcs(pR + 2*MS + j);
            float l3 = __ldcs(pR + 3*MS + j);
            float m0 = __ldcs(pI + j);
            float m1 = __ldcs(pI + MS + j);
            float m2 = __ldcs(pI + 2*MS + j);
            float m3 = __ldcs(pI + 3*MS + j);
            aR0 = fmaf(l0, ar, fmaf(m0, -ai, aR0));
            aI0 = fmaf(l0, ai, fmaf(m0,  ar, aI0));
            aR1 = fmaf(l1, ar, fmaf(m1, -ai, aR1));
            aI1 = fmaf(l1, ai, fmaf(m1,  ar, aI1));
            aR2 = fmaf(l2, ar, fmaf(m2, -ai, aR2));
            aI2 = fmaf(l2, ai, fmaf(m2,  ar, aI2));
            aR3 = fmaf(l3, ar, fmaf(m3, -ai, aR3));
            aI3 = fmaf(l3, ai, fmaf(m3,  ar, aI3));
        }
    }
#pragma unroll
    for (int off = 16; off; off >>= 1) {
        aR0 += __shfl_xor_sync(0xffffffffu, aR0, off);
        aR1 += __shfl_xor_sync(0xffffffffu, aR1, off);
        aR2 += __shfl_xor_sync(0xffffffffu, aR2, off);
        aR3 += __shfl_xor_sync(0xffffffffu, aR3, off);
        aI0 += __shfl_xor_sync(0xffffffffu, aI0, off);
        aI1 += __shfl_xor_sync(0xffffffffu, aI1, off);
        aI2 += __shfl_xor_sync(0xffffffffu, aI2, off);
        aI3 += __shfl_xor_sync(0xffffffffu, aI3, off);
    }
    if (lane == 0) {
        size_t o = (size_t)b * Mx * Nx + i;
        g_rowR[o]        = aR0;  g_rowI[o]        = aI0;
        g_rowR[o +   Nx] = aR1;  g_rowI[o +   Nx] = aI1;
        g_rowR[o + 2*Nx] = aR2;  g_rowI[o + 2*Nx] = aI2;
        g_rowR[o + 3*Nx] = aR3;  g_rowI[o + 3*Nx] = aI3;
    }
}

// ---------------- kernel D: fused output GEMM -------------------------------
// grid: 128 blocks, each handles 64 rows; 256 threads as 16x16, 4x4 reg tile.
// P_r = X_r @ W_r[m], P_i = X_i @ W_i[m], folded with rowR/rowI per m.
__global__ void __launch_bounds__(256) kD(const float* __restrict__ Xr,
                                          const float* __restrict__ Xi,
                                          const float* __restrict__ wr,
                                          const float* __restrict__ wi,
                                          float* __restrict__ out)
{
    __shared__ __align__(16) float Xr_s[64 * 72];   // [c][r], stride 72
    __shared__ __align__(16) float Xi_s[64 * 72];
    __shared__ float rR_s[4][64], rI_s[4][64];

    int r0 = blockIdx.x << 6;        // global row base (b*N + j)
    int b  = r0 >> 10;
    for (int idx = threadIdx.x; idx < 4096; idx += 256) {
        int r = idx >> 6, c = idx & 63;
        Xr_s[c*72 + r] = Xr[(size_t)(r0 + r)*64 + c];
        Xi_s[c*72 + r] = Xi[(size_t)(r0 + r)*64 + c];
    }
    {
        int m = threadIdx.x >> 6, r = threadIdx.x & 63;
        int jbase = r0 & 1023;
        rR_s[m][r] = g_rowR[(size_t)(b*4 + m)*Nx + jbase + r];
        rI_s[m][r] = g_rowI[(size_t)(b*4 + m)*Nx + jbase + r];
    }
    __syncthreads();

    int tx = threadIdx.x & 15, ty = threadIdx.x >> 4;
    int rr = ty << 2, oo = tx << 2;
    float aR[4][4], aI[4][4];
#pragma unroll
    for (int r = 0; r < 4; r++)
#pragma unroll
        for (int o = 0; o < 4; o++) { aR[r][o] = 0.f; aI[r][o] = 0.f; }

#pragma unroll
    for (int m = 0; m < 4; m++) {
        float pR[4][4], pI[4][4];
#pragma unroll
        for (int r = 0; r < 4; r++)
#pragma unroll
            for (int o = 0; o < 4; o++) { pR[r][o] = 0.f; pI[r][o] = 0.f; }

        const float4* wrp = (const float4*)(wr + (size_t)m * 64 * 64) + tx;
        const float4* wip = (const float4*)(wi + (size_t)m * 64 * 64) + tx;
#pragma unroll 8
        for (int c = 0; c < 64; c++) {
            float4 wv  = __ldg(wrp + c*16);
            float4 vv  = __ldg(wip + c*16);
            float4 xrv = *(const float4*)&Xr_s[c*72 + rr];
            float4 xiv = *(const float4*)&Xi_s[c*72 + rr];
            float xa[4] = {xrv.x, xrv.y, xrv.z, xrv.w};
            float ya[4] = {xiv.x, xiv.y, xiv.z, xiv.w};
            float wa[4] = {wv.x,  wv.y,  wv.z,  wv.w};
            float va[4] = {vv.x,  vv.y,  vv.z,  vv.w};
#pragma unroll
            for (int r = 0; r < 4; r++)
#pragma unroll
                for (int o = 0; o < 4; o++) {
                    pR[r][o] = fmaf(xa[r], wa[o], pR[r][o]);
                    pI[r][o] = fmaf(ya[r], va[o], pI[r][o]);
                }
        }
#pragma unroll
        for (int r = 0; r < 4; r++) {
            float cR = rR_s[m][rr + r], cI = rI_s[m][rr + r];
#pragma unroll
            for (int o = 0; o < 4; o++) {
                aR[r][o] = fmaf(cR, pR[r][o], fmaf(-cI, pI[r][o], aR[r][o]));
                aI[r][o] = fmaf(cI, pR[r][o], fmaf( cR, pI[r][o], aI[r][o]));
            }
        }
    }

#pragma unroll
    for (int r = 0; r < 4; r++) {
        size_t row = (size_t)(r0 + rr + r);
        float4 vr = make_float4(aR[r][0], aR[r][1], aR[r][2], aR[r][3]);
        float4 vi = make_float4(aI[r][0], aI[r][1], aI[r][2], aI[r][3]);
        *(float4*)(out + row*64 + oo)                 = vr;   // real block
        *(float4*)(out + (size_t)BNO + row*64 + oo)   = vi;   // imag block
    }
}

// ---------------- launch ----------------------------------------------------
extern "C" void kernel_launch(void* const* d_in, const int* in_sizes, int n_in,
                              void* d_out, int out_size)
{
    const float* Xr  = (const float*)d_in[0];
    const float* Xi  = (const float*)d_in[1];
    const float* Lr  = (const float*)d_in[2];
    const float* Li  = (const float*)d_in[3];
    const float* wr  = (const float*)d_in[4];
    const float* wi  = (const float*)d_in[5];
    const float* awr = (const float*)d_in[6];
    const float* awi = (const float*)d_in[7];
    const float* abr = (const float*)d_in[8];
    const float* abi = (const float*)d_in[9];
    const float* par = (const float*)d_in[10];
    const float* pai = (const float*)d_in[11];
    float* out = (float*)d_out;

    kA<<<BN/8, 256>>>(Xr, Xi, awr, awi);
    kB<<<Bx*256, 256>>>(abr, abi, par, pai);
    kC<<<Bx*128, 256>>>(Lr, Li, abr, abi, par, pai);
    kD<<<BN/64, 256>>>(Xr, Xi, wr, wi, out);
}

// round 2
// speedup vs baseline: 1.1192x; 1.1192x over previous
#include <cuda_runtime.h>
#include <math.h>

#define Bx 8
#define Nx 1024
#define Cx 64
#define Ox 64
#define Mx 4                 // K+1
#define BN (Bx*Nx)           // 8192
#define BNO (BN*Ox)          // 524288

// ---------------- scratch (device globals; no allocations allowed) ----------
__device__ float g_sRi[BN], g_sIi[BN], g_sRj[BN], g_sIj[BN];
__device__ float g_cmax[BN], g_rsum[BN];
__device__ float g_rowR[Bx*Mx*Nx], g_rowI[Bx*Mx*Nx];

// ---------------- kernel A: attention projections ---------------------------
__global__ void __launch_bounds__(256) kA(const float* __restrict__ Xr,
                                          const float* __restrict__ Xi,
                                          const float* __restrict__ awr,
                                          const float* __restrict__ awi)
{
    int gw   = (blockIdx.x * blockDim.x + threadIdx.x) >> 5;
    int lane = threadIdx.x & 31;
    if (gw >= BN) return;
    const float* xr = Xr + (size_t)gw * Cx;
    const float* xi = Xi + (size_t)gw * Cx;
    float a1=0.f,a2=0.f,a3=0.f,a4=0.f,a5=0.f,a6=0.f,a7=0.f,a8=0.f;
#pragma unroll
    for (int k = 0; k < 2; k++) {
        int c = lane + (k << 5);
        float xrv = xr[c], xiv = xi[c];
        float wri = awr[c],      wii = awi[c];
        float wrj = awr[Cx + c], wij = awi[Cx + c];
        a1 = fmaf(xrv, wri, a1);  a2 = fmaf(xiv, wii, a2);
        a3 = fmaf(xrv, wii, a3);  a4 = fmaf(xiv, wri, a4);
        a5 = fmaf(xrv, wrj, a5);  a6 = fmaf(xiv, wij, a6);
        a7 = fmaf(xrv, wij, a7);  a8 = fmaf(xiv, wrj, a8);
    }
#pragma unroll
    for (int off = 16; off; off >>= 1) {
        a1 += __shfl_xor_sync(0xffffffffu, a1, off);
        a2 += __shfl_xor_sync(0xffffffffu, a2, off);
        a3 += __shfl_xor_sync(0xffffffffu, a3, off);
        a4 += __shfl_xor_sync(0xffffffffu, a4, off);
        a5 += __shfl_xor_sync(0xffffffffu, a5, off);
        a6 += __shfl_xor_sync(0xffffffffu, a6, off);
        a7 += __shfl_xor_sync(0xffffffffu, a7, off);
        a8 += __shfl_xor_sync(0xffffffffu, a8, off);
    }
    if (lane == 0) {
        g_sRi[gw] = a1 - a2;
        g_sIi[gw] = a3 + a4;
        g_sRj[gw] = a5 - a6;
        g_sIj[gw] = a7 + a8;
    }
}

// ---------------- kernel B: per-(b,j) softmax stats over i ------------------
__global__ void __launch_bounds__(256) kB(const float* __restrict__ br,
                                          const float* __restrict__ bi,
                                          const float* __restrict__ par,
                                          const float* __restrict__ pai)
{
    __shared__ float sri_s[Nx], sii_s[Nx];
    __shared__ float red[8];
    int b  = blockIdx.x >> 8;
    int j0 = (blockIdx.x & 255) << 2;
    float biasr = br[0], biasi = bi[0];
    float apr = par[0], api = pai[0];
    for (int t = threadIdx.x; t < Nx; t += 256) {
        sri_s[t] = g_sRi[b*Nx + t] + biasr;
        sii_s[t] = g_sIi[b*Nx + t] + biasi;
    }
    __syncthreads();
    int lane = threadIdx.x & 31, wid = threadIdx.x >> 5;
    for (int jj = 0; jj < 4; jj++) {
        int j = j0 + jj;
        float sjr = g_sRj[b*Nx + j];
        float sji = g_sIj[b*Nx + j];
        float mags[4];
        float lmax = -1e30f;
#pragma unroll
        for (int k = 0; k < 4; k++) {
            int i = threadIdx.x + (k << 8);
            float scr = sri_s[i] + sjr;
            float sci = sii_s[i] + sji;
            float pr = scr >= 0.f ? scr : apr * scr;
            float pi = sci >= 0.f ? sci : api * sci;
            float s2 = fmaf(pr, pr, pi * pi);
            float rm = rsqrtf(fmaxf(s2, 1e-36f));
            float mg = s2 * rm;
            mags[k] = mg;
            lmax = fmaxf(lmax, mg);
        }
#pragma unroll
        for (int off = 16; off; off >>= 1)
            lmax = fmaxf(lmax, __shfl_xor_sync(0xffffffffu, lmax, off));
        if (lane == 0) red[wid] = lmax;
        __syncthreads();
        float M = red[0];
#pragma unroll
        for (int t = 1; t < 8; t++) M = fmaxf(M, red[t]);
        __syncthreads();
        float ls = 0.f;
#pragma unroll
        for (int k = 0; k < 4; k++) ls += __expf(mags[k] - M);
#pragma unroll
        for (int off = 16; off; off >>= 1)
            ls += __shfl_xor_sync(0xffffffffu, ls, off);
        if (lane == 0) red[wid] = ls;
        __syncthreads();
        if (threadIdx.x == 0) {
            float S = red[0]+red[1]+red[2]+red[3]+red[4]+red[5]+red[6]+red[7];
            g_cmax[b*Nx + j] = M;
            g_rsum[b*Nx + j] = 1.0f / S;
        }
        __syncthreads();
    }
}

// ---------------- kernel C: the 268 MB L reduction (HBM-bound) --------------
__global__ void __launch_bounds__(256) kC(const float* __restrict__ Lr,
                                          const float* __restrict__ Li,
                                          const float* __restrict__ br,
                                          const float* __restrict__ bi,
                                          const float* __restrict__ par,
                                          const float* __restrict__ pai)
{
    __shared__ float sjr_s[Nx], sji_s[Nx], cm_s[Nx], rs_s[Nx];
    int b  = blockIdx.x >> 7;
    int i0 = (blockIdx.x & 127) << 3;
    for (int t = threadIdx.x; t < Nx; t += 256) {
        sjr_s[t] = g_sRj[b*Nx + t];
        sji_s[t] = g_sIj[b*Nx + t];
        cm_s[t]  = g_cmax[b*Nx + t];
        rs_s[t]  = g_rsum[b*Nx + t];
    }
    __syncthreads();
    int wid = threadIdx.x >> 5, lane = threadIdx.x & 31;
    int i = i0 + wid;
    float sri = g_sRi[b*Nx + i] + br[0];
    float sii = g_sIi[b*Nx + i] + bi[0];
    float apr = par[0], api = pai[0];
    const size_t MS = (size_t)Nx * Nx;
    const float* pR = Lr + (size_t)b * Mx * MS + (size_t)i * Nx;
    const float* pI = Li + (size_t)b * Mx * MS + (size_t)i * Nx;

    float aR0=0.f,aR1=0.f,aR2=0.f,aR3=0.f;
    float aI0=0.f,aI1=0.f,aI2=0.f,aI3=0.f;

#pragma unroll 1
    for (int jb = 0; jb < Nx; jb += 64) {
#pragma unroll
        for (int u = 0; u < 2; u++) {
            int j = jb + (u << 5) + lane;
            float scr = sri + sjr_s[j];
            float sci = sii + sji_s[j];
            float pr = scr >= 0.f ? scr : apr * scr;
            float pi = sci >= 0.f ? sci : api * sci;
            float s2 = fmaf(pr, pr, pi * pi);
            float rm = rsqrtf(fmaxf(s2, 1e-36f));
            float mg = s2 * rm;
            float sc = __fdividef(__expf(mg - cm_s[j]) * rs_s[j], mg + 1e-12f);
            float ar = sc * pr, ai = sc * pi;
            float l0 = __ldcs(pR + j);
            float l1 = __ldcs(pR + MS + j);
            float l2 = __ldcs(pR + 2*MS + j);
            float l3 = __ldcs(pR + 3*MS + j);
            float m0 = __ldcs(pI + j);
            float m1 = __ldcs(pI + MS + j);
            float m2 = __ldcs(pI + 2*MS + j);
            float m3 = __ldcs(pI + 3*MS + j);
            aR0 = fmaf(l0, ar, fmaf(m0, -ai, aR0));
            aI0 = fmaf(l0, ai, fmaf(m0,  ar, aI0));
            aR1 = fmaf(l1, ar, fmaf(m1, -ai, aR1));
            aI1 = fmaf(l1, ai, fmaf(m1,  ar, aI1));
            aR2 = fmaf(l2, ar, fmaf(m2, -ai, aR2));
            aI2 = fmaf(l2, ai, fmaf(m2,  ar, aI2));
            aR3 = fmaf(l3, ar, fmaf(m3, -ai, aR3));
            aI3 = fmaf(l3, ai, fmaf(m3,  ar, aI3));
        }
    }
#pragma unroll
    for (int off = 16; off; off >>= 1) {
        aR0 += __shfl_xor_sync(0xffffffffu, aR0, off);
        aR1 += __shfl_xor_sync(0xffffffffu, aR1, off);
        aR2 += __shfl_xor_sync(0xffffffffu, aR2, off);
        aR3 += __shfl_xor_sync(0xffffffffu, aR3, off);
        aI0 += __shfl_xor_sync(0xffffffffu, aI0, off);
        aI1 += __shfl_xor_sync(0xffffffffu, aI1, off);
        aI2 += __shfl_xor_sync(0xffffffffu, aI2, off);
        aI3 += __shfl_xor_sync(0xffffffffu, aI3, off);
    }
    if (lane == 0) {
        size_t o = (size_t)b * Mx * Nx + i;
        g_rowR[o]        = aR0;  g_rowI[o]        = aI0;
        g_rowR[o +   Nx] = aR1;  g_rowI[o +   Nx] = aI1;
        g_rowR[o + 2*Nx] = aR2;  g_rowI[o + 2*Nx] = aI2;
        g_rowR[o + 3*Nx] = aR3;  g_rowI[o + 3*Nx] = aI3;
    }
}

// ---------------- kernel D v2: fused output GEMM (SMEM-staged weights) ------
// grid 256 blocks x 256 threads. Block: 32 rows x 64 outputs.
// Threads: tx = tid&15 (4 outputs), ty = tid>>4 (2 rows).
// Per-m phase: stage wr/wi (32KB) into SMEM, accumulate pR/pI from SMEM only,
// epilogue combines with rowR/rowI scalars held in registers.
// Dynamic SMEM 52224B -> up to 4 blocks/SM.
__global__ void __launch_bounds__(256) kD(const float* __restrict__ Xr,
                                          const float* __restrict__ Xi,
                                          const float* __restrict__ wr,
                                          const float* __restrict__ wi,
                                          float* __restrict__ out)
{
    extern __shared__ __align__(16) float sm[];
    float* Xr_s = sm;                 // [64][34]  (c-major, padded rows)
    float* Xi_s = sm + 2176;          // [64][34]
    float* wr_s = sm + 4352;          // [64][68]  (c-major, padded outputs)
    float* wi_s = sm + 8704;          // [64][68]

    int tid = threadIdx.x;
    int r0 = blockIdx.x << 5;         // 32 rows per block
    int b  = r0 >> 10;
    int jbase = r0 & 1023;

    // stage X tile (transposed): rows r0..r0+31, all 64 channels
    {
        // 1024 float4 reads total (32 rows * 16 groups * 2 tensors)
        for (int idx = tid; idx < 512; idx += 256) {
            int r = idx >> 4, cg = (idx & 15) << 2;
            float4 v = __ldg((const float4*)(Xr + (size_t)(r0 + r)*64 + cg));
            Xr_s[(cg+0)*34 + r] = v.x;
            Xr_s[(cg+1)*34 + r] = v.y;
            Xr_s[(cg+2)*34 + r] = v.z;
            Xr_s[(cg+3)*34 + r] = v.w;
            float4 u = __ldg((const float4*)(Xi + (size_t)(r0 + r)*64 + cg));
            Xi_s[(cg+0)*34 + r] = u.x;
            Xi_s[(cg+1)*34 + r] = u.y;
            Xi_s[(cg+2)*34 + r] = u.z;
            Xi_s[(cg+3)*34 + r] = u.w;
        }
    }

    int tx = tid & 15, ty = tid >> 4;
    int rl0 = ty << 1;                 // local rows rl0, rl0+1
    int oo  = tx << 2;                 // outputs oo..oo+3

    // per-thread combine scalars: cR/cI for 2 rows x 4 m
    float cR[Mx][2], cI[Mx][2];
#pragma unroll
    for (int m = 0; m < Mx; m++) {
#pragma unroll
        for (int r = 0; r < 2; r++) {
            size_t o = (size_t)(b*Mx + m)*Nx + jbase + rl0 + r;
            cR[m][r] = g_rowR[o];
            cI[m][r] = g_rowI[o];
        }
    }

    float aR[2][4], aI[2][4];
#pragma unroll
    for (int r = 0; r < 2; r++)
#pragma unroll
        for (int o = 0; o < 4; o++) { aR[r][o] = 0.f; aI[r][o] = 0.f; }

#pragma unroll 1
    for (int m = 0; m < Mx; m++) {
        __syncthreads();               // previous phase done reading w_s
        // stage weights for this m: 4096 floats each = 1024 float4
        {
            const float4* wrg = (const float4*)(wr + (size_t)m * 4096);
            const float4* wig = (const float4*)(wi + (size_t)m * 4096);
#pragma unroll
            for (int k = 0; k < 4; k++) {
                int idx = tid + (k << 8);      // 0..1023
                int c = idx >> 4, og = (idx & 15) << 2;
                *(float4*)&wr_s[c*68 + og] = __ldg(wrg + idx);
                *(float4*)&wi_s[c*68 + og] = __ldg(wig + idx);
            }
        }
        __syncthreads();

        float pR[2][4], pI[2][4];
#pragma unroll
        for (int r = 0; r < 2; r++)
#pragma unroll
            for (int o = 0; o < 4; o++) { pR[r][o] = 0.f; pI[r][o] = 0.f; }

#pragma unroll 8
        for (int c = 0; c < 64; c++) {
            float2 xrv = *(const float2*)&Xr_s[c*34 + rl0];
            float2 xiv = *(const float2*)&Xi_s[c*34 + rl0];
            float4 wv  = *(const float4*)&wr_s[c*68 + oo];
            float4 vv  = *(const float4*)&wi_s[c*68 + oo];
            float wa[4] = {wv.x, wv.y, wv.z, wv.w};
            float va[4] = {vv.x, vv.y, vv.z, vv.w};
            float xa[2] = {xrv.x, xrv.y};
            float ya[2] = {xiv.x, xiv.y};
#pragma unroll
            for (int r = 0; r < 2; r++)
#pragma unroll
                for (int o = 0; o < 4; o++) {
                    pR[r][o] = fmaf(xa[r], wa[o], pR[r][o]);
                    pI[r][o] = fmaf(ya[r], va[o], pI[r][o]);
                }
        }
#pragma unroll
        for (int r = 0; r < 2; r++)
#pragma unroll
            for (int o = 0; o < 4; o++) {
                aR[r][o] = fmaf(cR[m][r], pR[r][o], fmaf(-cI[m][r], pI[r][o], aR[r][o]));
                aI[r][o] = fmaf(cI[m][r], pR[r][o], fmaf( cR[m][r], pI[r][o], aI[r][o]));
            }
    }

#pragma unroll
    for (int r = 0; r < 2; r++) {
        size_t row = (size_t)(r0 + rl0 + r);
        float4 vr = make_float4(aR[r][0], aR[r][1], aR[r][2], aR[r][3]);
        float4 vi = make_float4(aI[r][0], aI[r][1], aI[r][2], aI[r][3]);
        *(float4*)(out + row*64 + oo)               = vr;   // real block
        *(float4*)(out + (size_t)BNO + row*64 + oo) = vi;   // imag block
    }
}

// ---------------- launch ----------------------------------------------------
extern "C" void kernel_launch(void* const* d_in, const int* in_sizes, int n_in,
                              void* d_out, int out_size)
{
    const float* Xr  = (const float*)d_in[0];
    const float* Xi  = (const float*)d_in[1];
    const float* Lr  = (const float*)d_in[2];
    const float* Li  = (const float*)d_in[3];
    const float* wr  = (const float*)d_in[4];
    const float* wi  = (const float*)d_in[5];
    const float* awr = (const float*)d_in[6];
    const float* awi = (const float*)d_in[7];
    const float* abr = (const float*)d_in[8];
    const float* abi = (const float*)d_in[9];
    const float* par = (const float*)d_in[10];
    const float* pai = (const float*)d_in[11];
    float* out = (float*)d_out;

    const int KD_SMEM = 13056 * 4;   // 52224 bytes
    static int attr_done = 0;
    if (!attr_done) {
        cudaFuncSetAttribute(kD, cudaFuncAttributeMaxDynamicSharedMemorySize, KD_SMEM);
        attr_done = 1;
    }

    kA<<<BN/8, 256>>>(Xr, Xi, awr, awi);
    kB<<<Bx*256, 256>>>(abr, abi, par, pai);
    kC<<<Bx*128, 256>>>(Lr, Li, abr, abi, par, pai);
    kD<<<BN/32, 256, KD_SMEM>>>(Xr, Xi, wr, wi, out);
}